// round 2
// baseline (speedup 1.0000x reference)
#include <cuda_runtime.h>
#include <math.h>

#define N_NODES 50000
#define N_EDGES 800000
#define H 128
#define LN_EPS 1e-5f

// Scratch: per-node projections. Layout [node][256]: cols 0..127 = P = x@Ws + b1,
// cols 128..255 = Q = x@Wr.  51.2 MB static device allocation (allowed).
__device__ float g_PQ[(size_t)N_NODES * 256];

// ---------------------------------------------------------------------------
// Kernel 1: node projection.  GEMM  [N_NODES x 128] @ [128 x 128] twice
// (blockIdx.y = 0 -> Ws (rows 0..127 of W1, +b1), 1 -> Wr (rows 128..255)).
// 64 rows/block, 256 threads, per-thread 8x4 register tile.
// ---------------------------------------------------------------------------
__global__ __launch_bounds__(256) void proj_kernel(const float* __restrict__ x,
                                                   const float* __restrict__ W1,
                                                   const float* __restrict__ b1) {
    __shared__ float As[128 * 64];   // As[k][m]  (transposed)
    __shared__ float Bs[32 * 128];   // Bs[k][o]  (staged 32-k chunk)

    const int tid  = threadIdx.x;
    const int half = blockIdx.y;            // 0 = P(Ws)+b1, 1 = Q(Wr)
    const int m0   = blockIdx.x * 64;
    const int eg   = tid >> 5;              // row group 0..7  (8 rows each)
    const int og   = tid & 31;              // col group 0..31 (4 cols each)

    // Load A tile transposed into SMEM (guard tail rows with zeros)
#pragma unroll
    for (int it = 0; it < 8; ++it) {
        int idx = tid + it * 256;
        int m   = idx & 63;
        int kg  = idx >> 6;                 // 0..31 -> k = 4*kg
        int n   = m0 + m;
        float4 v = make_float4(0.f, 0.f, 0.f, 0.f);
        if (n < N_NODES) v = *(const float4*)(x + (size_t)n * H + kg * 4);
        As[(kg * 4 + 0) * 64 + m] = v.x;
        As[(kg * 4 + 1) * 64 + m] = v.y;
        As[(kg * 4 + 2) * 64 + m] = v.z;
        As[(kg * 4 + 3) * 64 + m] = v.w;
    }

    float4 acc[8];
#pragma unroll
    for (int i = 0; i < 8; ++i) acc[i] = make_float4(0.f, 0.f, 0.f, 0.f);

    const float* B = W1 + (size_t)half * 128 * H;

    for (int kc = 0; kc < 4; ++kc) {
        __syncthreads();
        // stage 32 rows of B
#pragma unroll
        for (int it = 0; it < 4; ++it) {
            int idx = tid + it * 256;
            int o4  = idx & 31;
            int r   = idx >> 5;
            *(float4*)(Bs + r * 128 + o4 * 4) =
                *(const float4*)(B + (size_t)(kc * 32 + r) * H + o4 * 4);
        }
        __syncthreads();
#pragma unroll
        for (int k = 0; k < 32; ++k) {
            const float* ap = As + (kc * 32 + k) * 64 + eg * 8;
            float4 a0 = *(const float4*)(ap);
            float4 a1 = *(const float4*)(ap + 4);
            float4 b  = *(const float4*)(Bs + k * 128 + og * 4);
            float ar[8] = {a0.x, a0.y, a0.z, a0.w, a1.x, a1.y, a1.z, a1.w};
#pragma unroll
            for (int i = 0; i < 8; ++i) {
                acc[i].x += ar[i] * b.x;
                acc[i].y += ar[i] * b.y;
                acc[i].z += ar[i] * b.z;
                acc[i].w += ar[i] * b.w;
            }
        }
    }

    float4 bias = make_float4(0.f, 0.f, 0.f, 0.f);
    if (half == 0) bias = *(const float4*)(b1 + og * 4);

#pragma unroll
    for (int i = 0; i < 8; ++i) {
        int n = m0 + eg * 8 + i;
        if (n < N_NODES) {
            float4 v;
            v.x = acc[i].x + bias.x;
            v.y = acc[i].y + bias.y;
            v.z = acc[i].z + bias.z;
            v.w = acc[i].w + bias.w;
            *(float4*)(g_PQ + (size_t)n * 256 + half * 128 + og * 4) = v;
        }
    }
}

// ---------------------------------------------------------------------------
// Kernel 2: out = x  (residual preload; atomics then accumulate into out)
// ---------------------------------------------------------------------------
__global__ void init_kernel(float* __restrict__ out, const float* __restrict__ x) {
    int i = blockIdx.x * blockDim.x + threadIdx.x;
    if (i < N_NODES * H / 4) ((float4*)out)[i] = ((const float4*)x)[i];
}

// ---------------------------------------------------------------------------
// Kernel 3: edge GEMM  ef[64x128] @ We[128x128] per block, epilogue gathers
// P[s], Q[r], relu, atomicAdd into out[r].
// ---------------------------------------------------------------------------
__global__ __launch_bounds__(256) void edge_kernel(const float* __restrict__ ef,
                                                   const int* __restrict__ senders,
                                                   const int* __restrict__ receivers,
                                                   const float* __restrict__ W1,
                                                   float* __restrict__ out) {
    __shared__ float As[128 * 64];   // As[k][e]
    __shared__ float Bs[32 * 128];   // Bs[k][o]

    const int tid = threadIdx.x;
    const int e0  = blockIdx.x * 64;
    const int eg  = tid >> 5;
    const int og  = tid & 31;

#pragma unroll
    for (int it = 0; it < 8; ++it) {
        int idx = tid + it * 256;
        int e   = idx & 63;
        int kg  = idx >> 6;
        float4 v = *(const float4*)(ef + (size_t)(e0 + e) * H + kg * 4);
        As[(kg * 4 + 0) * 64 + e] = v.x;
        As[(kg * 4 + 1) * 64 + e] = v.y;
        As[(kg * 4 + 2) * 64 + e] = v.z;
        As[(kg * 4 + 3) * 64 + e] = v.w;
    }

    float4 acc[8];
#pragma unroll
    for (int i = 0; i < 8; ++i) acc[i] = make_float4(0.f, 0.f, 0.f, 0.f);

    const float* B = W1 + (size_t)256 * H;   // We = rows 256..383 of W1

    for (int kc = 0; kc < 4; ++kc) {
        __syncthreads();
#pragma unroll
        for (int it = 0; it < 4; ++it) {
            int idx = tid + it * 256;
            int o4  = idx & 31;
            int r   = idx >> 5;
            *(float4*)(Bs + r * 128 + o4 * 4) =
                *(const float4*)(B + (size_t)(kc * 32 + r) * H + o4 * 4);
        }
        __syncthreads();
#pragma unroll
        for (int k = 0; k < 32; ++k) {
            const float* ap = As + (kc * 32 + k) * 64 + eg * 8;
            float4 a0 = *(const float4*)(ap);
            float4 a1 = *(const float4*)(ap + 4);
            float4 b  = *(const float4*)(Bs + k * 128 + og * 4);
            float ar[8] = {a0.x, a0.y, a0.z, a0.w, a1.x, a1.y, a1.z, a1.w};
#pragma unroll
            for (int i = 0; i < 8; ++i) {
                acc[i].x += ar[i] * b.x;
                acc[i].y += ar[i] * b.y;
                acc[i].z += ar[i] * b.z;
                acc[i].w += ar[i] * b.w;
            }
        }
    }

    // Epilogue: msg = relu(acc + P[s] + Q[r]) ; atomic scatter to out[r]
#pragma unroll
    for (int i = 0; i < 8; ++i) {
        int e = e0 + eg * 8 + i;
        int s = senders[e];
        int r = receivers[e];
        const float4 p = *(const float4*)(g_PQ + (size_t)s * 256 + og * 4);
        const float4 q = *(const float4*)(g_PQ + (size_t)r * 256 + 128 + og * 4);
        float4 m;
        m.x = fmaxf(acc[i].x + p.x + q.x, 0.f);
        m.y = fmaxf(acc[i].y + p.y + q.y, 0.f);
        m.z = fmaxf(acc[i].z + p.z + q.z, 0.f);
        m.w = fmaxf(acc[i].w + p.w + q.w, 0.f);
        float* dst = out + (size_t)r * H + og * 4;
        atomicAdd(dst + 0, m.x);
        atomicAdd(dst + 1, m.y);
        atomicAdd(dst + 2, m.z);
        atomicAdd(dst + 3, m.w);
    }
}

// ---------------------------------------------------------------------------
// Kernel 4: in-place LayerNorm, one warp per row (8 rows / 256-thread block)
// ---------------------------------------------------------------------------
__global__ __launch_bounds__(256) void ln_kernel(float* __restrict__ out,
                                                 const float* __restrict__ gamma,
                                                 const float* __restrict__ beta) {
    int warp = threadIdx.x >> 5;
    int lane = threadIdx.x & 31;
    int row  = blockIdx.x * 8 + warp;
    if (row >= N_NODES) return;

    float4 h = *(const float4*)(out + (size_t)row * H + lane * 4);
    float s  = h.x + h.y + h.z + h.w;
    float s2 = h.x * h.x + h.y * h.y + h.z * h.z + h.w * h.w;
#pragma unroll
    for (int off = 16; off > 0; off >>= 1) {
        s  += __shfl_xor_sync(0xffffffffu, s, off);
        s2 += __shfl_xor_sync(0xffffffffu, s2, off);
    }
    float mean = s * (1.f / H);
    float var  = s2 * (1.f / H) - mean * mean;
    float rstd = rsqrtf(var + LN_EPS);

    float4 g = *(const float4*)(gamma + lane * 4);
    float4 b = *(const float4*)(beta + lane * 4);
    float4 o;
    o.x = g.x * (h.x - mean) * rstd + b.x;
    o.y = g.y * (h.y - mean) * rstd + b.y;
    o.z = g.z * (h.z - mean) * rstd + b.z;
    o.w = g.w * (h.w - mean) * rstd + b.w;
    *(float4*)(out + (size_t)row * H + lane * 4) = o;
}

// ---------------------------------------------------------------------------
extern "C" void kernel_launch(void* const* d_in, const int* in_sizes, int n_in,
                              void* d_out, int out_size) {
    const float* x         = (const float*)d_in[0];
    const int*   senders   = (const int*)d_in[1];
    const int*   receivers = (const int*)d_in[2];
    const float* ef        = (const float*)d_in[3];
    const float* W1        = (const float*)d_in[4];
    const float* b1        = (const float*)d_in[5];
    const float* gamma     = (const float*)d_in[6];
    const float* beta      = (const float*)d_in[7];
    float*       out       = (float*)d_out;

    proj_kernel<<<dim3((N_NODES + 63) / 64, 2), 256>>>(x, W1, b1);
    init_kernel<<<(N_NODES * H / 4 + 255) / 256, 256>>>(out, x);
    edge_kernel<<<N_EDGES / 64, 256>>>(ef, senders, receivers, W1, out);
    ln_kernel<<<N_NODES / 8, 256>>>(out, gamma, beta);
}

// round 3
// speedup vs baseline: 1.4152x; 1.4152x over previous
#include <cuda_runtime.h>
#include <math.h>
#include <stdint.h>

#define N_NODES 50000
#define N_EDGES 800000
#define H 128
#define LN_EPS 1e-5f

#define AS_STRIDE 132   // 64 x 132 fp32 (padded, conflict-free A-frag LDS)
#define BS_STRIDE 136   // 128 x 136 fp32 (padded, conflict-free B-frag LDS)
#define SMEM_EDGE ((64 * AS_STRIDE + 128 * BS_STRIDE) * 4)

// Scratch: per-node projections. [node][256]: 0..127 = P = x@Ws + b1, 128..255 = Q = x@Wr.
__device__ float g_PQ[(size_t)N_NODES * 256];

__device__ __forceinline__ float tf32r(float x) {
    uint32_t u;
    asm("cvt.rna.tf32.f32 %0, %1;" : "=r"(u) : "f"(x));
    return __uint_as_float(u);
}

__device__ __forceinline__ void mma_tf32(float d[4], uint32_t a0, uint32_t a1,
                                         uint32_t a2, uint32_t a3,
                                         uint32_t b0, uint32_t b1) {
    asm volatile(
        "mma.sync.aligned.m16n8k8.row.col.f32.tf32.tf32.f32 "
        "{%0,%1,%2,%3}, {%4,%5,%6,%7}, {%8,%9}, {%0,%1,%2,%3};"
        : "+f"(d[0]), "+f"(d[1]), "+f"(d[2]), "+f"(d[3])
        : "r"(a0), "r"(a1), "r"(a2), "r"(a3), "r"(b0), "r"(b1));
}

// ---------------------------------------------------------------------------
// Kernel 1: node projection (fp32 FFMA; only 3.3 GFLOP).
// blockIdx.y = 0 -> P = x@Ws + b1, 1 -> Q = x@Wr.
// ---------------------------------------------------------------------------
__global__ __launch_bounds__(256) void proj_kernel(const float* __restrict__ x,
                                                   const float* __restrict__ W1,
                                                   const float* __restrict__ b1) {
    __shared__ float As[128 * 64];
    __shared__ float Bs[32 * 128];

    const int tid  = threadIdx.x;
    const int half = blockIdx.y;
    const int m0   = blockIdx.x * 64;
    const int eg   = tid >> 5;
    const int og   = tid & 31;

#pragma unroll
    for (int it = 0; it < 8; ++it) {
        int idx = tid + it * 256;
        int m   = idx & 63;
        int kg  = idx >> 6;
        int n   = m0 + m;
        float4 v = make_float4(0.f, 0.f, 0.f, 0.f);
        if (n < N_NODES) v = *(const float4*)(x + (size_t)n * H + kg * 4);
        As[(kg * 4 + 0) * 64 + m] = v.x;
        As[(kg * 4 + 1) * 64 + m] = v.y;
        As[(kg * 4 + 2) * 64 + m] = v.z;
        As[(kg * 4 + 3) * 64 + m] = v.w;
    }

    float4 acc[8];
#pragma unroll
    for (int i = 0; i < 8; ++i) acc[i] = make_float4(0.f, 0.f, 0.f, 0.f);

    const float* B = W1 + (size_t)half * 128 * H;

    for (int kc = 0; kc < 4; ++kc) {
        __syncthreads();
#pragma unroll
        for (int it = 0; it < 4; ++it) {
            int idx = tid + it * 256;
            int o4  = idx & 31;
            int r   = idx >> 5;
            *(float4*)(Bs + r * 128 + o4 * 4) =
                *(const float4*)(B + (size_t)(kc * 32 + r) * H + o4 * 4);
        }
        __syncthreads();
#pragma unroll
        for (int k = 0; k < 32; ++k) {
            const float* ap = As + (kc * 32 + k) * 64 + eg * 8;
            float4 a0 = *(const float4*)(ap);
            float4 a1 = *(const float4*)(ap + 4);
            float4 b  = *(const float4*)(Bs + k * 128 + og * 4);
            float ar[8] = {a0.x, a0.y, a0.z, a0.w, a1.x, a1.y, a1.z, a1.w};
#pragma unroll
            for (int i = 0; i < 8; ++i) {
                acc[i].x += ar[i] * b.x;
                acc[i].y += ar[i] * b.y;
                acc[i].z += ar[i] * b.z;
                acc[i].w += ar[i] * b.w;
            }
        }
    }

    float4 bias = make_float4(0.f, 0.f, 0.f, 0.f);
    if (half == 0) bias = *(const float4*)(b1 + og * 4);

#pragma unroll
    for (int i = 0; i < 8; ++i) {
        int n = m0 + eg * 8 + i;
        if (n < N_NODES) {
            float4 v;
            v.x = acc[i].x + bias.x;
            v.y = acc[i].y + bias.y;
            v.z = acc[i].z + bias.z;
            v.w = acc[i].w + bias.w;
            *(float4*)(g_PQ + (size_t)n * 256 + half * 128 + og * 4) = v;
        }
    }
}

// ---------------------------------------------------------------------------
// Kernel 2: out = x (residual preload)
// ---------------------------------------------------------------------------
__global__ void init_kernel(float* __restrict__ out, const float* __restrict__ x) {
    int i = blockIdx.x * blockDim.x + threadIdx.x;
    if (i < N_NODES * H / 4) ((float4*)out)[i] = ((const float4*)x)[i];
}

// ---------------------------------------------------------------------------
// Kernel 3: edge GEMM on tf32 tensor cores.
// Block tile 64 edges x 128 out, K=128 fully resident in SMEM.
// 8 warps: 4 (m, 16 rows) x 2 (n, 64 cols). mma.m16n8k8 tf32.
// Epilogue: stage accum -> SMEM, gather P[s]/Q[r], relu, red.global.add.v4.
// ---------------------------------------------------------------------------
__global__ __launch_bounds__(256) void edge_kernel(const float* __restrict__ ef,
                                                   const int* __restrict__ senders,
                                                   const int* __restrict__ receivers,
                                                   const float* __restrict__ W1,
                                                   float* __restrict__ out) {
    extern __shared__ float smem_dyn[];
    float* As = smem_dyn;                       // [64][AS_STRIDE]  A[edge][k] (tf32)
    float* Bs = smem_dyn + 64 * AS_STRIDE;      // [128][BS_STRIDE] B[k][n]   (tf32)

    const int tid = threadIdx.x;
    const int e0  = blockIdx.x * 64;

    // Load A tile (edge_feat), round to tf32
#pragma unroll
    for (int it = 0; it < 8; ++it) {
        int idx = tid + it * 256;
        int e   = idx >> 5;
        int kg  = idx & 31;
        float4 v = *(const float4*)(ef + (size_t)(e0 + e) * H + kg * 4);
        v.x = tf32r(v.x); v.y = tf32r(v.y); v.z = tf32r(v.z); v.w = tf32r(v.w);
        *(float4*)(As + e * AS_STRIDE + kg * 4) = v;
    }

    // Load B tile (We = rows 256..383 of W1), round to tf32
    const float* B = W1 + (size_t)256 * H;
#pragma unroll
    for (int it = 0; it < 16; ++it) {
        int idx = tid + it * 256;
        int k   = idx >> 5;
        int o4  = idx & 31;
        float4 v = *(const float4*)(B + (size_t)k * H + o4 * 4);
        v.x = tf32r(v.x); v.y = tf32r(v.y); v.z = tf32r(v.z); v.w = tf32r(v.w);
        *(float4*)(Bs + k * BS_STRIDE + o4 * 4) = v;
    }
    __syncthreads();

    const int lane = tid & 31;
    const int wid  = tid >> 5;
    const int g    = lane >> 2;
    const int tig  = lane & 3;
    const int m_base = (wid & 3) * 16;
    const int n_base = (wid >> 2) * 64;

    float d[8][4];
#pragma unroll
    for (int j = 0; j < 8; ++j)
#pragma unroll
        for (int i = 0; i < 4; ++i) d[j][i] = 0.f;

#pragma unroll
    for (int ks = 0; ks < 16; ++ks) {
        const int k0 = ks * 8;
        const float* ar = As + (m_base + g) * AS_STRIDE + k0 + tig;
        uint32_t a0 = __float_as_uint(ar[0]);
        uint32_t a2 = __float_as_uint(ar[4]);
        uint32_t a1 = __float_as_uint(ar[8 * AS_STRIDE]);
        uint32_t a3 = __float_as_uint(ar[8 * AS_STRIDE + 4]);
        const float* br = Bs + (k0 + tig) * BS_STRIDE + n_base + g;
#pragma unroll
        for (int j = 0; j < 8; ++j) {
            uint32_t b0 = __float_as_uint(br[j * 8]);
            uint32_t b1 = __float_as_uint(br[4 * BS_STRIDE + j * 8]);
            mma_tf32(d[j], a0, a1, a2, a3, b0, b1);
        }
    }

    __syncthreads();  // all warps done reading As before we reuse it

    // Stage accumulators: Cs[edge_local][col], stride AS_STRIDE (row base 16B-aligned)
    float* Cs = smem_dyn;
#pragma unroll
    for (int j = 0; j < 8; ++j) {
        int c = n_base + j * 8 + 2 * tig;
        *(float2*)(Cs + (m_base + g) * AS_STRIDE + c)     = make_float2(d[j][0], d[j][1]);
        *(float2*)(Cs + (m_base + g + 8) * AS_STRIDE + c) = make_float2(d[j][2], d[j][3]);
    }
    __syncthreads();

    // Epilogue: msg = relu(Cs + P[s] + Q[r]); vector-atomic scatter into out[r]
    const int eg = tid >> 5;
    const int og = tid & 31;
#pragma unroll
    for (int i = 0; i < 8; ++i) {
        int el = eg * 8 + i;
        int e  = e0 + el;
        int s  = senders[e];
        int r  = receivers[e];
        float4 m = *(const float4*)(Cs + el * AS_STRIDE + og * 4);
        float4 p = *(const float4*)(g_PQ + (size_t)s * 256 + og * 4);
        float4 q = *(const float4*)(g_PQ + (size_t)r * 256 + 128 + og * 4);
        m.x = fmaxf(m.x + p.x + q.x, 0.f);
        m.y = fmaxf(m.y + p.y + q.y, 0.f);
        m.z = fmaxf(m.z + p.z + q.z, 0.f);
        m.w = fmaxf(m.w + p.w + q.w, 0.f);
        float* dst = out + (size_t)r * H + og * 4;
        asm volatile("red.global.add.v4.f32 [%0], {%1,%2,%3,%4};"
                     :: "l"(dst), "f"(m.x), "f"(m.y), "f"(m.z), "f"(m.w)
                     : "memory");
    }
}

// ---------------------------------------------------------------------------
// Kernel 4: in-place LayerNorm, one warp per row
// ---------------------------------------------------------------------------
__global__ __launch_bounds__(256) void ln_kernel(float* __restrict__ out,
                                                 const float* __restrict__ gamma,
                                                 const float* __restrict__ beta) {
    int warp = threadIdx.x >> 5;
    int lane = threadIdx.x & 31;
    int row  = blockIdx.x * 8 + warp;
    if (row >= N_NODES) return;

    float4 h = *(const float4*)(out + (size_t)row * H + lane * 4);
    float s  = h.x + h.y + h.z + h.w;
    float s2 = h.x * h.x + h.y * h.y + h.z * h.z + h.w * h.w;
#pragma unroll
    for (int off = 16; off > 0; off >>= 1) {
        s  += __shfl_xor_sync(0xffffffffu, s, off);
        s2 += __shfl_xor_sync(0xffffffffu, s2, off);
    }
    float mean = s * (1.f / H);
    float var  = s2 * (1.f / H) - mean * mean;
    float rstd = rsqrtf(var + LN_EPS);

    float4 g = *(const float4*)(gamma + lane * 4);
    float4 b = *(const float4*)(beta + lane * 4);
    float4 o;
    o.x = g.x * (h.x - mean) * rstd + b.x;
    o.y = g.y * (h.y - mean) * rstd + b.y;
    o.z = g.z * (h.z - mean) * rstd + b.z;
    o.w = g.w * (h.w - mean) * rstd + b.w;
    *(float4*)(out + (size_t)row * H + lane * 4) = o;
}

// ---------------------------------------------------------------------------
extern "C" void kernel_launch(void* const* d_in, const int* in_sizes, int n_in,
                              void* d_out, int out_size) {
    const float* x         = (const float*)d_in[0];
    const int*   senders   = (const int*)d_in[1];
    const int*   receivers = (const int*)d_in[2];
    const float* ef        = (const float*)d_in[3];
    const float* W1        = (const float*)d_in[4];
    const float* b1        = (const float*)d_in[5];
    const float* gamma     = (const float*)d_in[6];
    const float* beta      = (const float*)d_in[7];
    float*       out       = (float*)d_out;

    cudaFuncSetAttribute(edge_kernel, cudaFuncAttributeMaxDynamicSharedMemorySize,
                         SMEM_EDGE);

    proj_kernel<<<dim3((N_NODES + 63) / 64, 2), 256>>>(x, W1, b1);
    init_kernel<<<(N_NODES * H / 4 + 255) / 256, 256>>>(out, x);
    edge_kernel<<<N_EDGES / 64, 256, SMEM_EDGE>>>(ef, senders, receivers, W1, out);
    ln_kernel<<<N_NODES / 8, 256>>>(out, gamma, beta);
}